// round 12
// baseline (speedup 1.0000x reference)
#include <cuda_runtime.h>
#include <cuda_fp16.h>
#include <cstddef>

#define H 2048
#define H4 (H / 4)
#define NK 4
#define NSLOT 11              // 0=x, 1=h, 2..9=G[0..7] (raw S@M), 10=zero
#define ZSLOT 10
#define MAXP 64
#define MAXC 512
#define MULTC 0.001f
#define HSCALE 1024.0f
#define INVHSCALE (1.0f / 1024.0f)
#define NB 148
#define NT 512
#define NMV 128               // matvec worker blocks (8 mats x 16 dtiles)
#define FINB 128              // finalize block
#define ZERB 129              // S-zeroing block
#define HELP0 130             // helper blocks 130..147 do next-iter safe combos
#define NHELP 18
#define INIB 147              // init block (doubles as helper later)

// ---------------- persistent device state ----------------
__device__ __half d_M16[8][H][H];         // fp16 copy of L0..3,R0..3 (scaled by 1024)
__device__ float d_CLs[NSLOT][NK][H];
__device__ float d_CRs[NSLOT][NK][H];
__device__ float d_colL[NK][H];
__device__ float d_colR[NK][H];
__device__ float d_Sbuf[3][H];            // TRIPLE-buffered combo accumulation
__device__ float d_slotP[NSLOT], d_slotC4[NSLOT];
__device__ float d_cmax[MAXC], d_ssig[MAXC], d_stanh[MAXC], d_sres[MAXC];
__device__ int   d_pi[MAXP], d_pj[MAXP];
__device__ int   d_safeP[MAXP], d_unsafeP[MAXP];
__device__ int   d_nsafe, d_nunsafe;
__device__ int   d_npairs, d_nc;
__device__ int   d_candSlot[16];
__device__ int   d_cs[16], d_lc;
__device__ float d_sumw;
__device__ volatile int d_finFlag;        // generation: finalize(r) sets r+1

__device__ volatile unsigned int d_arrive[NB];
__device__ volatile unsigned int d_genv;

// ---------------- software grid barrier (tight spin) ----------------
__device__ __forceinline__ void gridbar(unsigned int& lg)
{
    __threadfence();
    __syncthreads();
    unsigned int target = lg + 1;
    if (threadIdx.x == 0) d_arrive[blockIdx.x] = target;
    if (blockIdx.x == 0) {
        if (threadIdx.x < NB) {
            while (d_arrive[threadIdx.x] != target) { }
        }
        __syncthreads();
        if (threadIdx.x == 0) d_genv = target;
    } else {
        if (threadIdx.x == 0) {
            while (d_genv != target) { }
        }
        __syncthreads();
    }
    __threadfence();
    lg = target;
}

// ---------------- one combo unit (global pair p, unit 0..7) ----------------
__device__ __forceinline__ void do_combo(int p, int unit, int tid,
                                         const float* __restrict__ b,
                                         const float* __restrict__ w,
                                         float& sl0, float& sl1, float& sl2, float& sl3,
                                         float (*sred)[4])
{
    int k = (unit >> 1) & 3;
    int isAdd = unit & 1;
    int c = p * 8 + unit;
    int si = d_candSlot[d_pi[p]];
    int sj = d_candSlot[d_pj[p]];
    float pA = d_slotP[si], cA = d_slotC4[si];
    float pB = d_slotP[sj], cB = d_slotC4[sj];
    const float* bk = b + k * H;

    float amax = 0.f, ssg = 0.f, sth = 0.f, srs = 0.f;
    #pragma unroll
    for (int u = 0; u < 4; ++u) {
        int e = tid + u * NT;
        float cl = pA * fmaf(cA, d_colL[k][e], d_CLs[si][k][e]);
        float cr = pB * fmaf(cB, d_colR[k][e], d_CRs[sj][k][e]);
        float res = isAdd ? ((cl + cr) + bk[e]) : fmaf(cl, cr, bk[e]);
        float uu = fminf(fmaxf(res, -30.f), 30.f);
        float t = __expf(-uu);
        float sg = 1.f / (1.f + t);
        float t2 = t * t;
        float th = (1.f - t2) / (1.f + t2);
        float we = w[e];
        amax = fmaxf(amax, fabsf(res));
        ssg = fmaf(sg, we, ssg);
        sth = fmaf(th, we, sth);
        srs = fmaf(res, we, srs);
        float add = MULTC * (sg + th);
        if (u == 0) sl0 += add; else if (u == 1) sl1 += add;
        else if (u == 2) sl2 += add; else sl3 += add;
    }
    int lane = tid & 31, wid = tid >> 5;
    for (int o = 16; o; o >>= 1) {
        amax = fmaxf(amax, __shfl_down_sync(0xffffffffu, amax, o));
        ssg += __shfl_down_sync(0xffffffffu, ssg, o);
        sth += __shfl_down_sync(0xffffffffu, sth, o);
        srs += __shfl_down_sync(0xffffffffu, srs, o);
    }
    if (lane == 0) { sred[wid][0] = amax; sred[wid][1] = ssg; sred[wid][2] = sth; sred[wid][3] = srs; }
    __syncthreads();
    if (tid == 0) {
        float A = sred[0][0], S1 = sred[0][1], S2 = sred[0][2], S3 = sred[0][3];
        for (int t = 1; t < 16; ++t) {
            A = fmaxf(A, sred[t][0]); S1 += sred[t][1]; S2 += sred[t][2]; S3 += sred[t][3];
        }
        d_cmax[c] = A; d_ssig[c] = S1; d_stanh[c] = S2; d_sres[c] = S3;
    }
    __syncthreads();
}

__global__ __launch_bounds__(NT, 1)
void rrnn_kernel(const float* __restrict__ L, const float* __restrict__ R,
                 const float* __restrict__ x, const float* __restrict__ h,
                 const float* __restrict__ b, const float* __restrict__ w,
                 float* __restrict__ out)
{
    __shared__ float4 sbuf4[NT * 3];
    float*  sb    = (float*)sbuf4;
    float4* sacc4 = sbuf4 + 2 * NT;
    __shared__ float sred[16][4];
    __shared__ float sh_gmax, sh_p, sh_c4;
    __shared__ int   sh_mi, sh_mj;
    __shared__ unsigned int s_lg;

    const int tid = threadIdx.x;
    const int bid = blockIdx.x;

    if (tid == 0) s_lg = d_genv;
    __syncthreads();
    unsigned int lg = s_lg;

    const int mb = bid >> 4;
    const int dt = bid & 15;
    const int q  = tid & 31;
    const int hs = tid >> 5;
    const float4* M4 = nullptr;
    if (bid < NMV)
        M4 = (const float4*)((mb < 4 ? L : R) + (size_t)(mb & 3) * H * H) + (dt * 32 + q);

    const int q16  = tid & 15;
    const int hs32 = tid >> 4;

    // ================= phase 0: prepass + fp16 copy + init =================
    if (bid < NMV) {
        float* sSx = sb;
        float* sSh = sb + H;
        for (int t = tid; t < H; t += NT) { sSx[t] = x[t]; sSh[t] = h[t]; }
        __syncthreads();
        float4 aX = {0,0,0,0}, aH = {0,0,0,0}, aO = {0,0,0,0};
        const int h0 = hs * 128;
        #pragma unroll 8
        for (int hh = h0; hh < h0 + 128; ++hh) {
            float4 v = M4[(size_t)hh * H4];
            union { __half2 h2[2]; uint2 u; } cv;
            cv.h2[0] = __floats2half2_rn(v.x * HSCALE, v.y * HSCALE);
            cv.h2[1] = __floats2half2_rn(v.z * HSCALE, v.w * HSCALE);
            *reinterpret_cast<uint2*>(&d_M16[mb][hh][dt * 128 + q * 4]) = cv.u;

            float gx = sSx[hh], gh = sSh[hh];
            aX.x = fmaf(gx, v.x, aX.x); aX.y = fmaf(gx, v.y, aX.y);
            aX.z = fmaf(gx, v.z, aX.z); aX.w = fmaf(gx, v.w, aX.w);
            aH.x = fmaf(gh, v.x, aH.x); aH.y = fmaf(gh, v.y, aH.y);
            aH.z = fmaf(gh, v.z, aH.z); aH.w = fmaf(gh, v.w, aH.w);
            aO.x += v.x; aO.y += v.y; aO.z += v.z; aO.w += v.w;
        }
        int k = mb & 3;
        float4* dstX = (float4*)(mb < 4 ? &d_CLs[0][k][0] : &d_CRs[0][k][0]);
        float4* dstH = (float4*)(mb < 4 ? &d_CLs[1][k][0] : &d_CRs[1][k][0]);
        float4* dstO = (float4*)(mb < 4 ? &d_colL[k][0]   : &d_colR[k][0]);
        #pragma unroll
        for (int pass = 0; pass < 3; ++pass) {
            float4 a = (pass == 0) ? aX : (pass == 1) ? aH : aO;
            __syncthreads();
            sacc4[tid] = a;
            __syncthreads();
            #pragma unroll
            for (int off = 8; off > 0; off >>= 1) {
                if (hs < off) {
                    float4 o = sacc4[tid + off * 32];
                    float4 s = sacc4[tid];
                    s.x += o.x; s.y += o.y; s.z += o.z; s.w += o.w;
                    sacc4[tid] = s;
                }
                __syncthreads();
            }
            if (tid < 32) {
                float4* dst = (pass == 0) ? dstX : (pass == 1) ? dstH : dstO;
                dst[dt * 32 + tid] = sacc4[tid];
            }
        }
    } else {
        if (bid == ZERB) {
            for (int t = tid; t < H; t += NT) { d_Sbuf[0][t] = 0.f; d_Sbuf[1][t] = 0.f; }
        }
        if (bid == INIB) {
            float s = 0.f;
            for (int t = tid; t < H; t += NT) s += w[t];
            sb[tid] = s;
            __syncthreads();
            for (int o = NT / 2; o > 0; o >>= 1) {
                if (tid < o) sb[tid] += sb[tid + o];
                __syncthreads();
            }
            if (tid == 0) {
                d_sumw = sb[0];
                d_finFlag = 0;
                d_lc = 0; d_nc = 3; d_npairs = 3;
                d_pi[0] = 0; d_pj[0] = 1;
                d_pi[1] = 0; d_pj[1] = 2;
                d_pi[2] = 1; d_pj[2] = 2;
                d_nunsafe = 3; d_nsafe = 0;
                d_unsafeP[0] = 0; d_unsafeP[1] = 1; d_unsafeP[2] = 2;
                d_candSlot[0] = 0; d_candSlot[1] = 1; d_candSlot[2] = ZSLOT;
                d_slotP[0] = 1.f; d_slotC4[0] = 0.f;
                d_slotP[1] = 1.f; d_slotC4[1] = 0.f;
                d_slotP[ZSLOT] = 0.f; d_slotC4[ZSLOT] = 0.f;
            }
        }
    }
    gridbar(lg);

    // ================= 9 iterations =================
    for (int r = 0; r < 9; ++r) {
        // ---------- phase A: UNSAFE combos only ----------
        int nU8 = d_nunsafe * 8;
        float* Sw = &d_Sbuf[r % 3][0];
        float sl0 = 0.f, sl1 = 0.f, sl2 = 0.f, sl3 = 0.f;
        bool didWork = false;
        for (int t = bid; t < nU8; t += NB) {
            didWork = true;
            do_combo(d_unsafeP[t >> 3], t & 7, tid, b, w, sl0, sl1, sl2, sl3, sred);
        }
        if (didWork) {
            atomicAdd(&Sw[tid + 0 * NT], sl0);
            atomicAdd(&Sw[tid + 1 * NT], sl1);
            atomicAdd(&Sw[tid + 2 * NT], sl2);
            atomicAdd(&Sw[tid + 3 * NT], sl3);
        }
        gridbar(lg);

        // ---------- phase B: matvec [0..127] || finalize [128] || zero [129] || safe combos [130..147] ----------
        if (bid < NMV && r < 8) {
            const bool rev = ((r & 1) == 0);
            float* sS = sb;
            float4* rlo = sbuf4 + 512;
            float4* rhi = sbuf4 + 1024;
            for (int t = tid; t < H; t += NT) sS[t] = Sw[t] * INVHSCALE;
            __syncthreads();

            const uint4* Mh = reinterpret_cast<const uint4*>(&d_M16[mb][0][dt * 128]) + q16;
            const int hb = hs32 * 64;
            const uint4* ptr = Mh + (size_t)(rev ? hb + 63 : hb) * (H / 8);
            const ptrdiff_t step = rev ? -(ptrdiff_t)(H / 8) : (ptrdiff_t)(H / 8);
            const float* sSp = rev ? (sS + hb + 63) : (sS + hb);
            const int sstep = rev ? -1 : 1;

            float a0=0,a1=0,a2=0,a3=0,a4=0,a5=0,a6=0,a7=0;
            #pragma unroll 8
            for (int i = 0; i < 64; ++i) {
                uint4 u = *ptr;
                float g = *sSp;
                ptr += step; sSp += sstep;
                float2 f0 = __half22float2(*reinterpret_cast<const __half2*>(&u.x));
                float2 f1 = __half22float2(*reinterpret_cast<const __half2*>(&u.y));
                float2 f2 = __half22float2(*reinterpret_cast<const __half2*>(&u.z));
                float2 f3 = __half22float2(*reinterpret_cast<const __half2*>(&u.w));
                a0 = fmaf(g, f0.x, a0); a1 = fmaf(g, f0.y, a1);
                a2 = fmaf(g, f1.x, a2); a3 = fmaf(g, f1.y, a3);
                a4 = fmaf(g, f2.x, a4); a5 = fmaf(g, f2.y, a5);
                a6 = fmaf(g, f3.x, a6); a7 = fmaf(g, f3.y, a7);
            }
            float4 alo = make_float4(a0, a1, a2, a3);
            float4 ahi = make_float4(a4, a5, a6, a7);
            __syncthreads();
            rlo[tid] = alo; rhi[tid] = ahi;
            __syncthreads();
            #pragma unroll
            for (int off = 16; off > 0; off >>= 1) {
                if (hs32 < off) {
                    float4 o1 = rlo[tid + off * 16];
                    float4 o2 = rhi[tid + off * 16];
                    alo.x += o1.x; alo.y += o1.y; alo.z += o1.z; alo.w += o1.w;
                    ahi.x += o2.x; ahi.y += o2.y; ahi.z += o2.z; ahi.w += o2.w;
                    rlo[tid] = alo; rhi[tid] = ahi;
                }
                __syncthreads();
            }
            if (hs32 == 0) {
                int k = mb & 3;
                int slot = 2 + r;
                float4* dst = (float4*)(mb < 4 ? &d_CLs[slot][k][0] : &d_CRs[slot][k][0]);
                dst[dt * 32 + q16 * 2]     = rlo[q16];
                dst[dt * 32 + q16 * 2 + 1] = rhi[q16];
            }
        } else if (bid == ZERB) {
            float* Sz = &d_Sbuf[(r + 2) % 3][0];
            for (int t = tid; t < H; t += NT) Sz[t] = 0.f;
        } else if (bid == FINB) {
            // ----- finalize -----
            float* sc4 = sb;
            float* rf  = sb + 2048;
            float* rmv = sb + 2560;
            int*   ri  = (int*)(sb + 3072);
            int*   rmk = (int*)(sb + 3584);
            unsigned char* s4 = (unsigned char*)(sb + 4096);

            int nn = d_npairs * 8;
            float sumw = d_sumw;
            for (int c = tid; c < nn; c += NT) {
                float sr = d_sres[c];
                sc4[c * 4 + 0] = MULTC * d_ssig[c];
                sc4[c * 4 + 1] = MULTC * d_stanh[c];
                sc4[c * 4 + 2] = sumw - sr;
                sc4[c * 4 + 3] = sr;
                s4[c] = (d_cmax[c] < 1.0f) ? 1 : 0;
            }
            __syncthreads();

            float mv = -3.0e38f; int mk = 0x7fffffff; int c4 = 0;
            for (int c = tid; c < nn; c += NT) {
                int cnt = s4[c] ? 4 : 2;
                c4 += (int)s4[c];
                for (int a2 = 0; a2 < cnt; ++a2) {
                    float v = sc4[c * 4 + a2];
                    int key = c * 4 + a2;
                    if (v > mv || (v == mv && key < mk)) { mv = v; mk = key; }
                }
            }
            rmv[tid] = mv; rmk[tid] = mk; ri[tid] = c4;
            __syncthreads();
            for (int s = NT / 2; s > 0; s >>= 1) {
                if (tid < s) {
                    if (rmv[tid + s] > rmv[tid] ||
                        (rmv[tid + s] == rmv[tid] && rmk[tid + s] < rmk[tid])) {
                        rmv[tid] = rmv[tid + s]; rmk[tid] = rmk[tid + s];
                    }
                    ri[tid] += ri[tid + s];
                }
                __syncthreads();
            }
            if (tid == 0) {
                sh_gmax = rmv[0];
                sh_c4 = (float)ri[0];
                int gmc = rmk[0] >> 2;
                sh_mi = d_pi[gmc >> 3];
                sh_mj = d_pj[gmc >> 3];
            }
            __syncthreads();
            float gmax = sh_gmax;
            float s1 = sc4[1];

            float se = 0.f; int rk = 0;
            for (int c = tid; c < nn; c += NT) {
                int cnt = s4[c] ? 4 : 2;
                for (int a2 = 0; a2 < cnt; ++a2) {
                    float v = sc4[c * 4 + a2];
                    se += expf(v - gmax);
                    rk += (v < s1) ? 1 : 0;
                }
            }
            rf[tid] = se; ri[tid] = rk;
            __syncthreads();
            for (int s = NT / 2; s > 0; s >>= 1) {
                if (tid < s) { rf[tid] += rf[tid + s]; ri[tid] += ri[tid + s]; }
                __syncthreads();
            }
            if (tid == 0) {
                float seT = rf[0];
                int rank = ri[0];
                int tA = d_nc - 2;
                float st = 0.f, ssec = 0.f;
                int cum = 0;
                for (int c = 0; c < nn; ++c) {
                    int cnt = s4[c] ? 4 : 2;
                    if (tA >= cum && tA < cum + cnt)     st   = sc4[c * 4 + (tA - cum)];
                    if (rank >= cum && rank < cum + cnt) ssec = sc4[c * 4 + (rank - cum)];
                    cum += cnt;
                }
                sh_p = expf(st - gmax) / seT;
                out[2048 + 9 * 2048 + 9 + r] = ssec;
            }
            __syncthreads();
            float p = sh_p, c4f = sh_c4;

            float dsw = 0.f;
            for (int e = tid; e < H; e += NT) {
                float Sv = Sw[e];
                float g = p * (Sv + c4f);
                out[2048 + r * 2048 + e] = g;
                if (r == 8) out[e] = g;
                dsw = fmaf(Sv, w[e], dsw);
            }
            rf[tid] = dsw;
            __syncthreads();
            for (int s = NT / 2; s > 0; s >>= 1) {
                if (tid < s) rf[tid] += rf[tid + s];
                __syncthreads();
            }
            if (tid == 0) {
                out[2048 + 9 * 2048 + r] = p * (rf[0] + c4f * d_sumw);

                d_slotP[2 + r] = p;
                d_slotC4[2 + r] = c4f;

                int i = sh_mi, j = sh_mj;
                int lc = d_lc;
                if (i > 2 && j > 2) {
                    d_cs[i - 3] = r;
                    for (int t = j - 3; t < lc - 1; ++t) d_cs[t] = d_cs[t + 1];
                    lc--;
                } else if (i <= 2 && j > 2) {
                    d_cs[j - 3] = r;
                } else {
                    d_cs[lc] = r; lc++;
                }
                d_lc = lc;

                if (r < 8) {
                    int nc2 = 3 + lc;
                    int nri = 9 - (r + 1);
                    int np = 0;
                    for (int a2 = 0; a2 < nc2 - 1; ++a2)
                        for (int bb = a2 + 1; bb < nc2; ++bb) {
                            bool flag;
                            if (nri == lc - 1)      flag = (a2 >= 3);
                            else if (nri == lc)     flag = (bb >= 3);
                            else                    flag = (nri > lc);
                            if (flag) { d_pi[np] = a2; d_pj[np] = bb; ++np; }
                        }
                    d_npairs = np; d_nc = nc2;
                    d_candSlot[0] = 0; d_candSlot[1] = 1; d_candSlot[2] = ZSLOT;
                    for (int t = 0; t < lc; ++t) d_candSlot[3 + t] = 2 + d_cs[t];

                    // classify pairs: unsafe iff either side is the new slot (2+r)
                    int newSlot = 2 + r;
                    int ns = 0, nu = 0;
                    for (int a2 = 0; a2 < np; ++a2) {
                        int sa = d_candSlot[d_pi[a2]];
                        int sb2 = d_candSlot[d_pj[a2]];
                        if (sa == newSlot || sb2 == newSlot) d_unsafeP[nu++] = a2;
                        else                                  d_safeP[ns++] = a2;
                    }
                    d_nsafe = ns; d_nunsafe = nu;
                    __threadfence();
                    d_finFlag = r + 1;        // publish to helper blocks
                }
            }
        } else if (bid >= HELP0 && r < 8) {
            // ----- helper blocks: SAFE combos of iteration r+1, overlapped with matvec -----
            if (tid == 0) {
                while (d_finFlag != r + 1) { }
                __threadfence();
            }
            __syncthreads();
            int nS8 = d_nsafe * 8;
            float* Sn = &d_Sbuf[(r + 1) % 3][0];
            float h0 = 0.f, h1 = 0.f, h2 = 0.f, h3 = 0.f;
            bool didW = false;
            for (int t = (bid - HELP0); t < nS8; t += NHELP) {
                didW = true;
                do_combo(d_safeP[t >> 3], t & 7, tid, b, w, h0, h1, h2, h3, sred);
            }
            if (didW) {
                atomicAdd(&Sn[tid + 0 * NT], h0);
                atomicAdd(&Sn[tid + 1 * NT], h1);
                atomicAdd(&Sn[tid + 2 * NT], h2);
                atomicAdd(&Sn[tid + 3 * NT], h3);
            }
        }
        if (r < 8) gridbar(lg);
    }
}

// ---------------- launch: ONE persistent kernel ----------------
extern "C" void kernel_launch(void* const* d_in, const int* in_sizes, int n_in,
                              void* d_out, int out_size)
{
    const float* x     = (const float*)d_in[0];
    const float* hprev = (const float*)d_in[1];
    const float* L     = (const float*)d_in[2];
    const float* R     = (const float*)d_in[3];
    const float* b     = (const float*)d_in[4];
    const float* w     = (const float*)d_in[5];
    float* out = (float*)d_out;

    rrnn_kernel<<<NB, NT>>>(L, R, x, hprev, b, w, out);
    (void)in_sizes; (void)n_in; (void)out_size;
}

// round 13
// speedup vs baseline: 1.2541x; 1.2541x over previous
#include <cuda_runtime.h>
#include <cuda_fp16.h>
#include <cstddef>

#define H 2048
#define H4 (H / 4)            // 512 float4 per fp32 matrix row
#define NK 4
#define NSLOT 11              // 0=x, 1=h, 2..9=G[0..7] (raw S@M), 10=zero
#define ZSLOT 10
#define MAXP 64
#define MAXC 512
#define MULTC 0.001f
#define HSCALE 1024.0f
#define INVHSCALE (1.0f / 1024.0f)
#define NB 296                // 2 blocks per SM
#define NT 512
#define NMV 256               // matvec worker blocks (8 mats x 32 half-tiles)
#define FINB 256              // finalize block
#define ZERB 257              // S-zeroing block
#define INIB 295              // init block

// ---------------- persistent device state ----------------
__device__ __half d_M16[8][H][H];         // fp16 copy of L0..3,R0..3 (scaled by 1024)
__device__ float d_CLs[NSLOT][NK][H];
__device__ float d_CRs[NSLOT][NK][H];
__device__ float d_colL[NK][H];
__device__ float d_colR[NK][H];
__device__ float d_Sbuf[2][H];
__device__ float d_slotP[NSLOT], d_slotC4[NSLOT];
__device__ float d_cmax[MAXC], d_ssig[MAXC], d_stanh[MAXC], d_sres[MAXC];
__device__ int   d_pi[MAXP], d_pj[MAXP];
__device__ int   d_npairs, d_nc;
__device__ int   d_candSlot[16];
__device__ int   d_cs[16], d_lc;
__device__ float d_sumw;

__device__ volatile unsigned int d_arrive[NB];
__device__ volatile unsigned int d_genv;

// ---------------- software grid barrier (tight spin) ----------------
__device__ __forceinline__ void gridbar(unsigned int& lg)
{
    __threadfence();
    __syncthreads();
    unsigned int target = lg + 1;
    if (threadIdx.x == 0) d_arrive[blockIdx.x] = target;
    if (blockIdx.x == 0) {
        if (threadIdx.x < NB) {
            while (d_arrive[threadIdx.x] != target) { }
        }
        __syncthreads();
        if (threadIdx.x == 0) d_genv = target;
    } else {
        if (threadIdx.x == 0) {
            while (d_genv != target) { }
        }
        __syncthreads();
    }
    __threadfence();
    lg = target;
}

__global__ __launch_bounds__(NT, 2)
void rrnn_kernel(const float* __restrict__ L, const float* __restrict__ R,
                 const float* __restrict__ x, const float* __restrict__ h,
                 const float* __restrict__ b, const float* __restrict__ w,
                 float* __restrict__ out)
{
    // 24KB shared scratch, aliased per phase
    __shared__ float4 sbuf4[NT * 3];
    float*  sb    = (float*)sbuf4;
    __shared__ float sred[16][4];
    __shared__ float sh_gmax, sh_p, sh_c4;
    __shared__ int   sh_mi, sh_mj;
    __shared__ unsigned int s_lg;

    const int tid = threadIdx.x;
    const int bid = blockIdx.x;

    if (tid == 0) s_lg = d_genv;
    __syncthreads();
    unsigned int lg = s_lg;

    // matvec geometry: 256 blocks = 8 mats x 32 half-tiles (64 cols each)
    const int mb = bid >> 5;              // matrix 0..7 (0..3 = L_k, 4..7 = R_k)
    const int dt = bid & 31;              // half-tile (64 floats = 16 float4)
    // fp32 prepass lanes: 16 col-quads x 32 h-segments of 64 rows
    const int q  = tid & 15;
    const int hs = tid >> 4;              // 0..31
    const float4* M4 = nullptr;
    if (bid < NMV)
        M4 = (const float4*)((mb < 4 ? L : R) + (size_t)(mb & 3) * H * H) + (dt * 16 + q);

    // fp16 sweep lanes: 8 uint4-cols x 64 h-segments of 32 rows
    const int q8   = tid & 7;
    const int hs64 = tid >> 3;            // 0..63

    // ================= phase 0: prepass (x, h, ones; fp32) + fp16 copy + init =================
    if (bid < NMV) {
        float* sSx = sb;                  // floats [0:2048)
        float* sSh = sb + H;              // floats [2048:4096)
        float4* sacc4 = sbuf4 + 1024;     // float4 [1024:1536)
        for (int t = tid; t < H; t += NT) { sSx[t] = x[t]; sSh[t] = h[t]; }
        __syncthreads();
        float4 aX = {0,0,0,0}, aH = {0,0,0,0}, aO = {0,0,0,0};
        const int h0 = hs * 64;
        #pragma unroll 8
        for (int hh = h0; hh < h0 + 64; ++hh) {
            float4 v = M4[(size_t)hh * H4];
            union { __half2 h2[2]; uint2 u; } cv;
            cv.h2[0] = __floats2half2_rn(v.x * HSCALE, v.y * HSCALE);
            cv.h2[1] = __floats2half2_rn(v.z * HSCALE, v.w * HSCALE);
            *reinterpret_cast<uint2*>(&d_M16[mb][hh][dt * 64 + q * 4]) = cv.u;

            float gx = sSx[hh], gh = sSh[hh];
            aX.x = fmaf(gx, v.x, aX.x); aX.y = fmaf(gx, v.y, aX.y);
            aX.z = fmaf(gx, v.z, aX.z); aX.w = fmaf(gx, v.w, aX.w);
            aH.x = fmaf(gh, v.x, aH.x); aH.y = fmaf(gh, v.y, aH.y);
            aH.z = fmaf(gh, v.z, aH.z); aH.w = fmaf(gh, v.w, aH.w);
            aO.x += v.x; aO.y += v.y; aO.z += v.z; aO.w += v.w;
        }
        int k = mb & 3;
        float4* dstX = (float4*)(mb < 4 ? &d_CLs[0][k][0] : &d_CRs[0][k][0]);
        float4* dstH = (float4*)(mb < 4 ? &d_CLs[1][k][0] : &d_CRs[1][k][0]);
        float4* dstO = (float4*)(mb < 4 ? &d_colL[k][0]   : &d_colR[k][0]);
        #pragma unroll
        for (int pass = 0; pass < 3; ++pass) {
            float4 a = (pass == 0) ? aX : (pass == 1) ? aH : aO;
            __syncthreads();
            sacc4[tid] = a;
            __syncthreads();
            #pragma unroll
            for (int off = 16; off > 0; off >>= 1) {
                if (hs < off) {
                    float4 o = sacc4[tid + off * 16];
                    float4 s = sacc4[tid];
                    s.x += o.x; s.y += o.y; s.z += o.z; s.w += o.w;
                    sacc4[tid] = s;
                }
                __syncthreads();
            }
            if (tid < 16) {
                float4* dst = (pass == 0) ? dstX : (pass == 1) ? dstH : dstO;
                dst[dt * 16 + tid] = sacc4[tid];
            }
        }
    } else {
        if (bid == ZERB) {
            for (int t = tid; t < H; t += NT) { d_Sbuf[0][t] = 0.f; d_Sbuf[1][t] = 0.f; }
        }
        if (bid == INIB) {
            float s = 0.f;
            for (int t = tid; t < H; t += NT) s += w[t];
            sb[tid] = s;
            __syncthreads();
            for (int o = NT / 2; o > 0; o >>= 1) {
                if (tid < o) sb[tid] += sb[tid + o];
                __syncthreads();
            }
            if (tid == 0) {
                d_sumw = sb[0];
                d_lc = 0; d_nc = 3; d_npairs = 3;
                d_pi[0] = 0; d_pj[0] = 1;
                d_pi[1] = 0; d_pj[1] = 2;
                d_pi[2] = 1; d_pj[2] = 2;
                d_candSlot[0] = 0; d_candSlot[1] = 1; d_candSlot[2] = ZSLOT;
                d_slotP[0] = 1.f; d_slotC4[0] = 0.f;
                d_slotP[1] = 1.f; d_slotC4[1] = 0.f;
                d_slotP[ZSLOT] = 0.f; d_slotC4[ZSLOT] = 0.f;
            }
        }
    }
    gridbar(lg);

    // ================= 9 iterations =================
    for (int r = 0; r < 9; ++r) {
        // ---------- phase A: combos ----------
        int n = d_npairs * 8;
        float* Sw = &d_Sbuf[r & 1][0];
        float sl0 = 0.f, sl1 = 0.f, sl2 = 0.f, sl3 = 0.f;
        for (int c = bid; c < n; c += NB) {
            int p = c >> 3;
            int k = (c >> 1) & 3;
            int isAdd = c & 1;
            int si = d_candSlot[d_pi[p]];
            int sj = d_candSlot[d_pj[p]];
            float pA = d_slotP[si], cA = d_slotC4[si];
            float pB = d_slotP[sj], cB = d_slotC4[sj];
            const float* bk = b + k * H;

            float amax = 0.f, ssg = 0.f, sth = 0.f, srs = 0.f;
            #pragma unroll
            for (int u = 0; u < 4; ++u) {
                int e = tid + u * NT;
                float cl = pA * fmaf(cA, d_colL[k][e], d_CLs[si][k][e]);
                float cr = pB * fmaf(cB, d_colR[k][e], d_CRs[sj][k][e]);
                float res = isAdd ? ((cl + cr) + bk[e]) : fmaf(cl, cr, bk[e]);
                float uu = fminf(fmaxf(res, -30.f), 30.f);
                float t = __expf(-uu);
                float sg = 1.f / (1.f + t);
                float t2 = t * t;
                float th = (1.f - t2) / (1.f + t2);
                float we = w[e];
                amax = fmaxf(amax, fabsf(res));
                ssg = fmaf(sg, we, ssg);
                sth = fmaf(th, we, sth);
                srs = fmaf(res, we, srs);
                float add = MULTC * (sg + th);
                if (u == 0) sl0 += add; else if (u == 1) sl1 += add;
                else if (u == 2) sl2 += add; else sl3 += add;
            }
            int lane = tid & 31, wid = tid >> 5;
            for (int o = 16; o; o >>= 1) {
                amax = fmaxf(amax, __shfl_down_sync(0xffffffffu, amax, o));
                ssg += __shfl_down_sync(0xffffffffu, ssg, o);
                sth += __shfl_down_sync(0xffffffffu, sth, o);
                srs += __shfl_down_sync(0xffffffffu, srs, o);
            }
            if (lane == 0) { sred[wid][0] = amax; sred[wid][1] = ssg; sred[wid][2] = sth; sred[wid][3] = srs; }
            __syncthreads();
            if (tid == 0) {
                float A = sred[0][0], S1 = sred[0][1], S2 = sred[0][2], S3 = sred[0][3];
                for (int t = 1; t < 16; ++t) {
                    A = fmaxf(A, sred[t][0]); S1 += sred[t][1]; S2 += sred[t][2]; S3 += sred[t][3];
                }
                d_cmax[c] = A; d_ssig[c] = S1; d_stanh[c] = S2; d_sres[c] = S3;
            }
            __syncthreads();
        }
        if (bid < n) {
            atomicAdd(&Sw[tid + 0 * NT], sl0);
            atomicAdd(&Sw[tid + 1 * NT], sl1);
            atomicAdd(&Sw[tid + 2 * NT], sl2);
            atomicAdd(&Sw[tid + 3 * NT], sl3);
        }
        gridbar(lg);

        // ---------- phase B: fp16 matvec(S_r) [0..255]  ||  finalize [256]  ||  zero [257] ----------
        if (bid < NMV && r < 8) {
            const bool rev = ((r & 1) == 0);
            float* sS = sb;                                // floats [0:2048) = float4 [0:512)
            float4* rlo = sbuf4 + 512;                     // float4 [512:1024)
            float4* rhi = sbuf4 + 1024;                    // float4 [1024:1536)
            for (int t = tid; t < H; t += NT) sS[t] = Sw[t] * INVHSCALE;
            __syncthreads();

            const uint4* Mh = reinterpret_cast<const uint4*>(&d_M16[mb][0][dt * 64]) + q8;
            const int hb = hs64 * 32;
            const uint4* ptr = Mh + (size_t)(rev ? hb + 31 : hb) * (H / 8);
            const ptrdiff_t step = rev ? -(ptrdiff_t)(H / 8) : (ptrdiff_t)(H / 8);
            const float* sSp = rev ? (sS + hb + 31) : (sS + hb);
            const int sstep = rev ? -1 : 1;

            float a0=0,a1=0,a2=0,a3=0,a4=0,a5=0,a6=0,a7=0;
            #pragma unroll 8
            for (int i = 0; i < 32; ++i) {
                uint4 u = *ptr;
                float g = *sSp;
                ptr += step; sSp += sstep;
                float2 f0 = __half22float2(*reinterpret_cast<const __half2*>(&u.x));
                float2 f1 = __half22float2(*reinterpret_cast<const __half2*>(&u.y));
                float2 f2 = __half22float2(*reinterpret_cast<const __half2*>(&u.z));
                float2 f3 = __half22float2(*reinterpret_cast<const __half2*>(&u.w));
                a0 = fmaf(g, f0.x, a0); a1 = fmaf(g, f0.y, a1);
                a2 = fmaf(g, f1.x, a2); a3 = fmaf(g, f1.y, a3);
                a4 = fmaf(g, f2.x, a4); a5 = fmaf(g, f2.y, a5);
                a6 = fmaf(g, f3.x, a6); a7 = fmaf(g, f3.y, a7);
            }
            float4 alo = make_float4(a0, a1, a2, a3);
            float4 ahi = make_float4(a4, a5, a6, a7);
            __syncthreads();
            rlo[tid] = alo; rhi[tid] = ahi;
            __syncthreads();
            #pragma unroll
            for (int off = 32; off > 0; off >>= 1) {
                if (hs64 < off) {
                    float4 o1 = rlo[tid + off * 8];
                    float4 o2 = rhi[tid + off * 8];
                    alo.x += o1.x; alo.y += o1.y; alo.z += o1.z; alo.w += o1.w;
                    ahi.x += o2.x; ahi.y += o2.y; ahi.z += o2.z; ahi.w += o2.w;
                    rlo[tid] = alo; rhi[tid] = ahi;
                }
                __syncthreads();
            }
            if (hs64 == 0) {
                int k = mb & 3;
                int slot = 2 + r;
                float4* dst = (float4*)(mb < 4 ? &d_CLs[slot][k][0] : &d_CRs[slot][k][0]);
                dst[dt * 16 + q8 * 2]     = rlo[q8];
                dst[dt * 16 + q8 * 2 + 1] = rhi[q8];
            }
        } else if (bid == ZERB) {
            float* Sz = &d_Sbuf[(r + 1) & 1][0];
            for (int t = tid; t < H; t += NT) Sz[t] = 0.f;
        } else if (bid == FINB) {
            // ----- finalize -----
            float* sc4 = sb;                              // floats [0:2048)
            float* rf  = sb + 2048;
            float* rmv = sb + 2560;
            int*   ri  = (int*)(sb + 3072);
            int*   rmk = (int*)(sb + 3584);
            unsigned char* s4 = (unsigned char*)(sb + 4096);

            int nn = n;
            float sumw = d_sumw;
            for (int c = tid; c < nn; c += NT) {
                float sr = d_sres[c];
                sc4[c * 4 + 0] = MULTC * d_ssig[c];
                sc4[c * 4 + 1] = MULTC * d_stanh[c];
                sc4[c * 4 + 2] = sumw - sr;
                sc4[c * 4 + 3] = sr;
                s4[c] = (d_cmax[c] < 1.0f) ? 1 : 0;
            }
            __syncthreads();

            float mv = -3.0e38f; int mk = 0x7fffffff; int c4 = 0;
            for (int c = tid; c < nn; c += NT) {
                int cnt = s4[c] ? 4 : 2;
                c4 += (int)s4[c];
                for (int a2 = 0; a2 < cnt; ++a2) {
                    float v = sc4[c * 4 + a2];
                    int key = c * 4 + a2;
                    if (v > mv || (v == mv && key < mk)) { mv = v; mk = key; }
                }
            }
            rmv[tid] = mv; rmk[tid] = mk; ri[tid] = c4;
            __syncthreads();
            for (int s = NT / 2; s > 0; s >>= 1) {
                if (tid < s) {
                    if (rmv[tid + s] > rmv[tid] ||
                        (rmv[tid + s] == rmv[tid] && rmk[tid + s] < rmk[tid])) {
                        rmv[tid] = rmv[tid + s]; rmk[tid] = rmk[tid + s];
                    }
                    ri[tid] += ri[tid + s];
                }
                __syncthreads();
            }
            if (tid == 0) {
                sh_gmax = rmv[0];
                sh_c4 = (float)ri[0];
                int gmc = rmk[0] >> 2;
                sh_mi = d_pi[gmc >> 3];
                sh_mj = d_pj[gmc >> 3];
            }
            __syncthreads();
            float gmax = sh_gmax;
            float s1 = sc4[1];

            float se = 0.f; int rk = 0;
            for (int c = tid; c < nn; c += NT) {
                int cnt = s4[c] ? 4 : 2;
                for (int a2 = 0; a2 < cnt; ++a2) {
                    float v = sc4[c * 4 + a2];
                    se += expf(v - gmax);
                    rk += (v < s1) ? 1 : 0;
                }
            }
            rf[tid] = se; ri[tid] = rk;
            __syncthreads();
            for (int s = NT / 2; s > 0; s >>= 1) {
                if (tid < s) { rf[tid] += rf[tid + s]; ri[tid] += ri[tid + s]; }
                __syncthreads();
            }
            if (tid == 0) {
                float seT = rf[0];
                int rank = ri[0];
                int tA = d_nc - 2;
                float st = 0.f, ssec = 0.f;
                int cum = 0;
                for (int c = 0; c < nn; ++c) {
                    int cnt = s4[c] ? 4 : 2;
                    if (tA >= cum && tA < cum + cnt)     st   = sc4[c * 4 + (tA - cum)];
                    if (rank >= cum && rank < cum + cnt) ssec = sc4[c * 4 + (rank - cum)];
                    cum += cnt;
                }
                sh_p = expf(st - gmax) / seT;
                out[2048 + 9 * 2048 + 9 + r] = ssec;
            }
            __syncthreads();
            float p = sh_p, c4f = sh_c4;

            float dsw = 0.f;
            for (int e = tid; e < H; e += NT) {
                float Sv = Sw[e];
                float g = p * (Sv + c4f);
                out[2048 + r * 2048 + e] = g;
                if (r == 8) out[e] = g;
                dsw = fmaf(Sv, w[e], dsw);
            }
            rf[tid] = dsw;
            __syncthreads();
            for (int s = NT / 2; s > 0; s >>= 1) {
                if (tid < s) rf[tid] += rf[tid + s];
                __syncthreads();
            }
            if (tid == 0) {
                out[2048 + 9 * 2048 + r] = p * (rf[0] + c4f * d_sumw);

                d_slotP[2 + r] = p;
                d_slotC4[2 + r] = c4f;

                int i = sh_mi, j = sh_mj;
                int lc = d_lc;
                if (i > 2 && j > 2) {
                    d_cs[i - 3] = r;
                    for (int t = j - 3; t < lc - 1; ++t) d_cs[t] = d_cs[t + 1];
                    lc--;
                } else if (i <= 2 && j > 2) {
                    d_cs[j - 3] = r;
                } else {
                    d_cs[lc] = r; lc++;
                }
                d_lc = lc;

                if (r < 8) {
                    int nc2 = 3 + lc;
                    int nri = 9 - (r + 1);
                    int np = 0;
                    for (int a2 = 0; a2 < nc2 - 1; ++a2)
                        for (int bb = a2 + 1; bb < nc2; ++bb) {
                            bool flag;
                            if (nri == lc - 1)      flag = (a2 >= 3);
                            else if (nri == lc)     flag = (bb >= 3);
                            else                    flag = (nri > lc);
                            if (flag) { d_pi[np] = a2; d_pj[np] = bb; ++np; }
                        }
                    d_npairs = np; d_nc = nc2;
                    d_candSlot[0] = 0; d_candSlot[1] = 1; d_candSlot[2] = ZSLOT;
                    for (int t = 0; t < lc; ++t) d_candSlot[3 + t] = 2 + d_cs[t];
                }
            }
        }
        if (r < 8) gridbar(lg);
    }
}

// ---------------- launch: ONE persistent kernel ----------------
extern "C" void kernel_launch(void* const* d_in, const int* in_sizes, int n_in,
                              void* d_out, int out_size)
{
    const float* x     = (const float*)d_in[0];
    const float* hprev = (const float*)d_in[1];
    const float* L     = (const float*)d_in[2];
    const float* R     = (const float*)d_in[3];
    const float* b     = (const float*)d_in[4];
    const float* w     = (const float*)d_in[5];
    float* out = (float*)d_out;

    rrnn_kernel<<<NB, NT>>>(L, R, x, hprev, b, w, out);
    (void)in_sizes; (void)n_in; (void)out_size;
}

// round 14
// speedup vs baseline: 1.3911x; 1.1093x over previous
#include <cuda_runtime.h>
#include <cuda_fp16.h>
#include <cstddef>

#define H 2048
#define H4 (H / 4)            // 512 float4 per matrix row
#define NK 4
#define NSLOT 11              // 0=x, 1=h, 2..9=G[0..7] (raw S@M), 10=zero
#define ZSLOT 10
#define MAXP 64
#define MAXC 512
#define MULTC 0.001f
#define HSCALE 1024.0f
#define INVHSCALE (1.0f / 1024.0f)
#define NB 148
#define NT 512
#define NMV 128               // matvec worker blocks (8 mats x 16 dtiles)
#define FINB 128              // finalize block
#define ZERB 129              // S-zeroing block
#define INIB 147              // init block

// ---------------- persistent device state ----------------
__device__ __half d_M16[8][H][H];         // fp16 copy of L0..3,R0..3 (scaled by 1024)
__device__ float d_CLs[NSLOT][NK][H];     // raw matvec results (S@L_k per slot)
__device__ float d_CRs[NSLOT][NK][H];
__device__ float d_colL[NK][H];           // ones @ L_k (column sums)
__device__ float d_colR[NK][H];
__device__ float d_Sbuf[2][H];            // double-buffered combo accumulation
__device__ float d_slotP[NSLOT], d_slotC4[NSLOT];
__device__ float d_cmax[MAXC], d_ssig[MAXC], d_stanh[MAXC], d_sres[MAXC];
__device__ int   d_pi[MAXP], d_pj[MAXP];
__device__ int   d_npairs, d_nc;
__device__ int   d_candSlot[16];
__device__ int   d_cs[16], d_lc;
__device__ float d_sumw;

__device__ unsigned int d_count;          // monotonic barrier arrivals
__device__ unsigned int d_genv;           // quiescent d_count value at launch entry

// ---------------- counter-based grid barrier (no leader hop) ----------------
__device__ __forceinline__ void gridbar(unsigned int& lg)
{
    __threadfence();
    __syncthreads();
    unsigned int target = lg + NB;
    if (threadIdx.x == 0) {
        atomicAdd(&d_count, 1u);
        while ((int)(*(volatile unsigned int*)&d_count - target) < 0) { }
    }
    __syncthreads();
    __threadfence();
    lg = target;
}

__global__ __launch_bounds__(NT, 1)
void rrnn_kernel(const float* __restrict__ L, const float* __restrict__ R,
                 const float* __restrict__ x, const float* __restrict__ h,
                 const float* __restrict__ b, const float* __restrict__ w,
                 float* __restrict__ out)
{
    // 24KB shared scratch, aliased per phase
    __shared__ float4 sbuf4[NT * 3];
    float*  sb    = (float*)sbuf4;
    float4* sacc4 = sbuf4 + 2 * NT;       // reduction scratch (prepass)
    __shared__ float sred[16][4];
    __shared__ float sh_gmax, sh_p, sh_c4;
    __shared__ int   sh_mi, sh_mj;
    __shared__ unsigned int s_lg;

    const int tid = threadIdx.x;
    const int bid = blockIdx.x;

    if (tid == 0) s_lg = d_genv;          // stable: only rewritten at end of prior launch
    __syncthreads();
    unsigned int lg = s_lg;

    // matvec geometry
    const int mb = bid >> 4;              // matrix 0..7 (0..3 = L_k, 4..7 = R_k)
    const int dt = bid & 15;              // d-tile (128 floats)
    const int q  = tid & 31;              // fp32 prepass: float4 column within tile
    const int hs = tid >> 5;              // fp32 prepass: h-segment (16 segs x 128)
    const float4* M4 = nullptr;
    if (bid < NMV)
        M4 = (const float4*)((mb < 4 ? L : R) + (size_t)(mb & 3) * H * H) + (dt * 32 + q);

    // fp16 matvec geometry: 16 col-lanes x 8 cols, 32 h-segs x 64 rows
    const int q16  = tid & 15;
    const int hs32 = tid >> 4;

    // ================= phase 0: prepass (x, h, ones; fp32) + write fp16 copy + init =================
    if (bid < NMV) {
        float* sSx = sb;                  // [0:2048)
        float* sSh = sb + H;              // [2048:4096)
        for (int t = tid; t < H; t += NT) { sSx[t] = x[t]; sSh[t] = h[t]; }
        __syncthreads();
        float4 aX = {0,0,0,0}, aH = {0,0,0,0}, aO = {0,0,0,0};
        const int h0 = hs * 128;
        #pragma unroll 8
        for (int hh = h0; hh < h0 + 128; ++hh) {
            float4 v = M4[(size_t)hh * H4];
            // fp16 scaled copy (x1024)
            union { __half2 h2[2]; uint2 u; } cv;
            cv.h2[0] = __floats2half2_rn(v.x * HSCALE, v.y * HSCALE);
            cv.h2[1] = __floats2half2_rn(v.z * HSCALE, v.w * HSCALE);
            *reinterpret_cast<uint2*>(&d_M16[mb][hh][dt * 128 + q * 4]) = cv.u;

            float gx = sSx[hh], gh = sSh[hh];
            aX.x = fmaf(gx, v.x, aX.x); aX.y = fmaf(gx, v.y, aX.y);
            aX.z = fmaf(gx, v.z, aX.z); aX.w = fmaf(gx, v.w, aX.w);
            aH.x = fmaf(gh, v.x, aH.x); aH.y = fmaf(gh, v.y, aH.y);
            aH.z = fmaf(gh, v.z, aH.z); aH.w = fmaf(gh, v.w, aH.w);
            aO.x += v.x; aO.y += v.y; aO.z += v.z; aO.w += v.w;
        }
        int k = mb & 3;
        float4* dstX = (float4*)(mb < 4 ? &d_CLs[0][k][0] : &d_CRs[0][k][0]);
        float4* dstH = (float4*)(mb < 4 ? &d_CLs[1][k][0] : &d_CRs[1][k][0]);
        float4* dstO = (float4*)(mb < 4 ? &d_colL[k][0]   : &d_colR[k][0]);
        // three sequential tree reductions over h-segments
        #pragma unroll
        for (int pass = 0; pass < 3; ++pass) {
            float4 a = (pass == 0) ? aX : (pass == 1) ? aH : aO;
            __syncthreads();
            sacc4[tid] = a;
            __syncthreads();
            #pragma unroll
            for (int off = 8; off > 0; off >>= 1) {
                if (hs < off) {
                    float4 o = sacc4[tid + off * 32];
                    float4 s = sacc4[tid];
                    s.x += o.x; s.y += o.y; s.z += o.z; s.w += o.w;
                    sacc4[tid] = s;
                }
                __syncthreads();
            }
            if (tid < 32) {
                float4* dst = (pass == 0) ? dstX : (pass == 1) ? dstH : dstO;
                dst[dt * 32 + tid] = sacc4[tid];
            }
        }
    } else {
        if (bid == ZERB) {
            for (int t = tid; t < H; t += NT) { d_Sbuf[0][t] = 0.f; d_Sbuf[1][t] = 0.f; }
        }
        if (bid == INIB) {
            float s = 0.f;
            for (int t = tid; t < H; t += NT) s += w[t];
            sb[tid] = s;
            __syncthreads();
            for (int o = NT / 2; o > 0; o >>= 1) {
                if (tid < o) sb[tid] += sb[tid + o];
                __syncthreads();
            }
            if (tid == 0) {
                d_sumw = sb[0];
                d_lc = 0; d_nc = 3; d_npairs = 3;
                d_pi[0] = 0; d_pj[0] = 1;
                d_pi[1] = 0; d_pj[1] = 2;
                d_pi[2] = 1; d_pj[2] = 2;
                d_candSlot[0] = 0; d_candSlot[1] = 1; d_candSlot[2] = ZSLOT;
                d_slotP[0] = 1.f; d_slotC4[0] = 0.f;
                d_slotP[1] = 1.f; d_slotC4[1] = 0.f;
                d_slotP[ZSLOT] = 0.f; d_slotC4[ZSLOT] = 0.f;
            }
        }
    }
    gridbar(lg);

    // ================= 9 iterations =================
    for (int r = 0; r < 9; ++r) {
        // ---------- phase A: combos ----------
        int n = d_npairs * 8;
        float* Sw = &d_Sbuf[r & 1][0];
        float sl0 = 0.f, sl1 = 0.f, sl2 = 0.f, sl3 = 0.f;
        for (int c = bid; c < n; c += NB) {
            int p = c >> 3;
            int k = (c >> 1) & 3;
            int isAdd = c & 1;
            int si = d_candSlot[d_pi[p]];
            int sj = d_candSlot[d_pj[p]];
            float pA = d_slotP[si], cA = d_slotC4[si];
            float pB = d_slotP[sj], cB = d_slotC4[sj];
            const float* bk = b + k * H;

            float amax = 0.f, ssg = 0.f, sth = 0.f, srs = 0.f;
            #pragma unroll
            for (int u = 0; u < 4; ++u) {
                int e = tid + u * NT;
                float cl = pA * fmaf(cA, d_colL[k][e], d_CLs[si][k][e]);
                float cr = pB * fmaf(cB, d_colR[k][e], d_CRs[sj][k][e]);
                float res = isAdd ? ((cl + cr) + bk[e]) : fmaf(cl, cr, bk[e]);
                float uu = fminf(fmaxf(res, -30.f), 30.f);
                float t = __expf(-uu);
                float sg = 1.f / (1.f + t);
                float t2 = t * t;
                float th = (1.f - t2) / (1.f + t2);
                float we = w[e];
                amax = fmaxf(amax, fabsf(res));
                ssg = fmaf(sg, we, ssg);
                sth = fmaf(th, we, sth);
                srs = fmaf(res, we, srs);
                float add = MULTC * (sg + th);
                if (u == 0) sl0 += add; else if (u == 1) sl1 += add;
                else if (u == 2) sl2 += add; else sl3 += add;
            }
            int lane = tid & 31, wid = tid >> 5;
            for (int o = 16; o; o >>= 1) {
                amax = fmaxf(amax, __shfl_down_sync(0xffffffffu, amax, o));
                ssg += __shfl_down_sync(0xffffffffu, ssg, o);
                sth += __shfl_down_sync(0xffffffffu, sth, o);
                srs += __shfl_down_sync(0xffffffffu, srs, o);
            }
            if (lane == 0) { sred[wid][0] = amax; sred[wid][1] = ssg; sred[wid][2] = sth; sred[wid][3] = srs; }
            __syncthreads();
            if (tid == 0) {
                float A = sred[0][0], S1 = sred[0][1], S2 = sred[0][2], S3 = sred[0][3];
                for (int t = 1; t < 16; ++t) {
                    A = fmaxf(A, sred[t][0]); S1 += sred[t][1]; S2 += sred[t][2]; S3 += sred[t][3];
                }
                d_cmax[c] = A; d_ssig[c] = S1; d_stanh[c] = S2; d_sres[c] = S3;
            }
            __syncthreads();
        }
        if (bid < n) {
            atomicAdd(&Sw[tid + 0 * NT], sl0);
            atomicAdd(&Sw[tid + 1 * NT], sl1);
            atomicAdd(&Sw[tid + 2 * NT], sl2);
            atomicAdd(&Sw[tid + 3 * NT], sl3);
        }
        gridbar(lg);

        // ---------- phase B: fp16 matvec(S_r) [0..127]  ||  finalize [128]  ||  zero [129] ----------
        if (bid < NMV && r < 8) {
            // zigzag direction (sweep r+1; prepass was ascending)
            const bool rev = ((r & 1) == 0);
            float* sS = sb;                                // [0:2048) floats
            float4* rlo = sbuf4 + 512;                     // [2048:4096) floats
            float4* rhi = sbuf4 + 1024;                    // [4096:6144) floats
            for (int t = tid; t < H; t += NT) sS[t] = Sw[t] * INVHSCALE;
            __syncthreads();

            const uint4* Mh = reinterpret_cast<const uint4*>(&d_M16[mb][0][dt * 128]) + q16;
            const int hb = hs32 * 64;
            const uint4* ptr = Mh + (size_t)(rev ? hb + 63 : hb) * (H / 8);
            const ptrdiff_t step = rev ? -(ptrdiff_t)(H / 8) : (ptrdiff_t)(H / 8);
            const float* sSp = rev ? (sS + hb + 63) : (sS + hb);
            const int sstep = rev ? -1 : 1;

            float a0=0,a1=0,a2=0,a3=0,a4=0,a5=0,a6=0,a7=0;
            #pragma unroll 8
            for (int i = 0; i < 64; ++i) {
                uint4 u = *ptr;
                float g = *sSp;
                ptr += step; sSp += sstep;
                float2 f0 = __half22float2(*reinterpret_cast<const __half2*>(&u.x));
                float2 f1 = __half22float2(*reinterpret_cast<const __half2*>(&u.y));
                float2 f2 = __half22float2(*reinterpret_cast<const __half2*>(&u.z));
                float2 f3 = __half22float2(*reinterpret_cast<const __half2*>(&u.w));
                a0 = fmaf(g, f0.x, a0); a1 = fmaf(g, f0.y, a1);
                a2 = fmaf(g, f1.x, a2); a3 = fmaf(g, f1.y, a3);
                a4 = fmaf(g, f2.x, a4); a5 = fmaf(g, f2.y, a5);
                a6 = fmaf(g, f3.x, a6); a7 = fmaf(g, f3.y, a7);
            }
            float4 alo = make_float4(a0, a1, a2, a3);
            float4 ahi = make_float4(a4, a5, a6, a7);
            __syncthreads();
            rlo[tid] = alo; rhi[tid] = ahi;
            __syncthreads();
            #pragma unroll
            for (int off = 16; off > 0; off >>= 1) {
                if (hs32 < off) {
                    float4 o1 = rlo[tid + off * 16];
                    float4 o2 = rhi[tid + off * 16];
                    alo.x += o1.x; alo.y += o1.y; alo.z += o1.z; alo.w += o1.w;
                    ahi.x += o2.x; ahi.y += o2.y; ahi.z += o2.z; ahi.w += o2.w;
                    rlo[tid] = alo; rhi[tid] = ahi;
                }
                __syncthreads();
            }
            if (hs32 == 0) {
                int k = mb & 3;
                int slot = 2 + r;
                float4* dst = (float4*)(mb < 4 ? &d_CLs[slot][k][0] : &d_CRs[slot][k][0]);
                dst[dt * 32 + q16 * 2]     = rlo[q16];
                dst[dt * 32 + q16 * 2 + 1] = rhi[q16];
            }
        } else if (bid == ZERB) {
            float* Sz = &d_Sbuf[(r + 1) & 1][0];
            for (int t = tid; t < H; t += NT) Sz[t] = 0.f;
        } else if (bid == FINB) {
            // ----- finalize -----
            float* sc4 = sb;                              // [0:2048)
            float* rf  = sb + 2048;                       // [2048:2560)
            float* rmv = sb + 2560;                       // [2560:3072)
            int*   ri  = (int*)(sb + 3072);               // [3072:3584)
            int*   rmk = (int*)(sb + 3584);               // [3584:4096)
            unsigned char* s4 = (unsigned char*)(sb + 4096);  // 512 bytes

            int nn = n;
            float sumw = d_sumw;
            for (int c = tid; c < nn; c += NT) {
                float sr = d_sres[c];
                sc4[c * 4 + 0] = MULTC * d_ssig[c];
                sc4[c * 4 + 1] = MULTC * d_stanh[c];
                sc4[c * 4 + 2] = sumw - sr;
                sc4[c * 4 + 3] = sr;
                s4[c] = (d_cmax[c] < 1.0f) ? 1 : 0;
            }
            __syncthreads();

            // pass 1: argmax (first-occurrence ties) + count4
            float mv = -3.0e38f; int mk = 0x7fffffff; int c4 = 0;
            for (int c = tid; c < nn; c += NT) {
                int cnt = s4[c] ? 4 : 2;
                c4 += (int)s4[c];
                for (int a2 = 0; a2 < cnt; ++a2) {
                    float v = sc4[c * 4 + a2];
                    int key = c * 4 + a2;
                    if (v > mv || (v == mv && key < mk)) { mv = v; mk = key; }
                }
            }
            rmv[tid] = mv; rmk[tid] = mk; ri[tid] = c4;
            __syncthreads();
            for (int s = NT / 2; s > 0; s >>= 1) {
                if (tid < s) {
                    if (rmv[tid + s] > rmv[tid] ||
                        (rmv[tid + s] == rmv[tid] && rmk[tid + s] < rmk[tid])) {
                        rmv[tid] = rmv[tid + s]; rmk[tid] = rmk[tid + s];
                    }
                    ri[tid] += ri[tid + s];
                }
                __syncthreads();
            }
            if (tid == 0) {
                sh_gmax = rmv[0];
                sh_c4 = (float)ri[0];
                int gmc = rmk[0] >> 2;
                sh_mi = d_pi[gmc >> 3];
                sh_mj = d_pj[gmc >> 3];
            }
            __syncthreads();
            float gmax = sh_gmax;
            float s1 = sc4[1];

            // pass 2: sumexp + rank(s1)
            float se = 0.f; int rk = 0;
            for (int c = tid; c < nn; c += NT) {
                int cnt = s4[c] ? 4 : 2;
                for (int a2 = 0; a2 < cnt; ++a2) {
                    float v = sc4[c * 4 + a2];
                    se += expf(v - gmax);
                    rk += (v < s1) ? 1 : 0;
                }
            }
            rf[tid] = se; ri[tid] = rk;
            __syncthreads();
            for (int s = NT / 2; s > 0; s >>= 1) {
                if (tid < s) { rf[tid] += rf[tid + s]; ri[tid] += ri[tid + s]; }
                __syncthreads();
            }
            if (tid == 0) {
                float seT = rf[0];
                int rank = ri[0];
                int tA = d_nc - 2;
                float st = 0.f, ssec = 0.f;
                int cum = 0;
                for (int c = 0; c < nn; ++c) {
                    int cnt = s4[c] ? 4 : 2;
                    if (tA >= cum && tA < cum + cnt)     st   = sc4[c * 4 + (tA - cum)];
                    if (rank >= cum && rank < cum + cnt) ssec = sc4[c * 4 + (rank - cum)];
                    cum += cnt;
                }
                sh_p = expf(st - gmax) / seT;
                out[2048 + 9 * 2048 + 9 + r] = ssec;
            }
            __syncthreads();
            float p = sh_p, c4f = sh_c4;

            float dsw = 0.f;
            for (int e = tid; e < H; e += NT) {
                float Sv = Sw[e];
                float g = p * (Sv + c4f);
                out[2048 + r * 2048 + e] = g;
                if (r == 8) out[e] = g;
                dsw = fmaf(Sv, w[e], dsw);
            }
            rf[tid] = dsw;
            __syncthreads();
            for (int s = NT / 2; s > 0; s >>= 1) {
                if (tid < s) rf[tid] += rf[tid + s];
                __syncthreads();
            }
            if (tid == 0) {
                out[2048 + 9 * 2048 + r] = p * (rf[0] + c4f * d_sumw);

                d_slotP[2 + r] = p;
                d_slotC4[2 + r] = c4f;

                int i = sh_mi, j = sh_mj;
                int lc = d_lc;
                if (i > 2 && j > 2) {
                    d_cs[i - 3] = r;
                    for (int t = j - 3; t < lc - 1; ++t) d_cs[t] = d_cs[t + 1];
                    lc--;
                } else if (i <= 2 && j > 2) {
                    d_cs[j - 3] = r;
                } else {
                    d_cs[lc] = r; lc++;
                }
                d_lc = lc;

                if (r < 8) {
                    int nc2 = 3 + lc;
                    int nri = 9 - (r + 1);
                    int np = 0;
                    for (int a2 = 0; a2 < nc2 - 1; ++a2)
                        for (int bb = a2 + 1; bb < nc2; ++bb) {
                            bool flag;
                            if (nri == lc - 1)      flag = (a2 >= 3);
                            else if (nri == lc)     flag = (bb >= 3);
                            else                    flag = (nri > lc);
                            if (flag) { d_pi[np] = a2; d_pj[np] = bb; ++np; }
                        }
                    d_npairs = np; d_nc = nc2;
                    d_candSlot[0] = 0; d_candSlot[1] = 1; d_candSlot[2] = ZSLOT;
                    for (int t = 0; t < lc; ++t) d_candSlot[3 + t] = 2 + d_cs[t];
                }
            }
        }
        if (r < 8) gridbar(lg);
    }

    // publish quiescent counter value for the next graph replay (idempotent)
    if (tid == 0) d_genv = lg;
}

// ---------------- launch: ONE persistent kernel ----------------
extern "C" void kernel_launch(void* const* d_in, const int* in_sizes, int n_in,
                              void* d_out, int out_size)
{
    const float* x     = (const float*)d_in[0];
    const float* hprev = (const float*)d_in[1];
    const float* L     = (const float*)d_in[2];
    const float* R     = (const float*)d_in[3];
    const float* b     = (const float*)d_in[4];
    const float* w     = (const float*)d_in[5];
    float* out = (float*)d_out;

    rrnn_kernel<<<NB, NT>>>(L, R, x, hprev, b, w, out);
    (void)in_sizes; (void)n_in; (void)out_size;
}

// round 15
// speedup vs baseline: 1.3998x; 1.0062x over previous
#include <cuda_runtime.h>
#include <cuda_fp16.h>
#include <cstddef>

#define H 2048
#define H4 (H / 4)            // 512 float4 per matrix row
#define NK 4
#define NSLOT 11              // 0=x, 1=h, 2..9=G[0..7] (raw S@M), 10=zero
#define ZSLOT 10
#define MAXP 64
#define MAXC 512
#define MULTC 0.001f
#define HSCALE 1024.0f
#define INVHSCALE (1.0f / 1024.0f)
#define NB 148
#define NT 512
#define NMV 128               // matvec worker blocks (8 mats x 16 dtiles)
#define FINB 128              // finalize block
#define ZERB 129              // S-zeroing block
#define INIB 147              // init block

#define SMEM_SCRATCH 24576            // 24KB aliased scratch (as before)
#define SMROWS 640                    // stripe rows cached in persistent smem
#define SMBYTES (SMROWS * 256)        // 160KB
#define SMEM_TOTAL (SMEM_SCRATCH + SMBYTES)

// ---------------- persistent device state ----------------
__device__ __half d_M16[8][H][H];         // fp16 copy of L0..3,R0..3 (scaled by 1024)
__device__ float d_CLs[NSLOT][NK][H];     // raw matvec results (S@L_k per slot)
__device__ float d_CRs[NSLOT][NK][H];
__device__ float d_colL[NK][H];           // ones @ L_k (column sums)
__device__ float d_colR[NK][H];
__device__ float d_Sbuf[2][H];            // double-buffered combo accumulation
__device__ float d_slotP[NSLOT], d_slotC4[NSLOT];
__device__ float d_cmax[MAXC], d_ssig[MAXC], d_stanh[MAXC], d_sres[MAXC];
__device__ int   d_pi[MAXP], d_pj[MAXP];
__device__ int   d_npairs, d_nc;
__device__ int   d_candSlot[16];
__device__ int   d_cs[16], d_lc;
__device__ float d_sumw;

__device__ unsigned int d_count;          // monotonic barrier arrivals
__device__ unsigned int d_genv;           // quiescent d_count value at launch entry

// ---------------- counter-based grid barrier (no leader hop) ----------------
__device__ __forceinline__ void gridbar(unsigned int& lg)
{
    __threadfence();
    __syncthreads();
    unsigned int target = lg + NB;
    if (threadIdx.x == 0) {
        atomicAdd(&d_count, 1u);
        while ((int)(*(volatile unsigned int*)&d_count - target) < 0) { }
    }
    __syncthreads();
    __threadfence();
    lg = target;
}

__global__ __launch_bounds__(NT, 1)
void rrnn_kernel(const float* __restrict__ L, const float* __restrict__ R,
                 const float* __restrict__ x, const float* __restrict__ h,
                 const float* __restrict__ b, const float* __restrict__ w,
                 float* __restrict__ out)
{
    extern __shared__ float4 dynbuf[];
    float*  sb    = (float*)dynbuf;            // 24KB scratch, aliased per phase
    float4* sacc4 = dynbuf + 2 * NT;           // reduction scratch (prepass)
    char*   sMat  = (char*)dynbuf + SMEM_SCRATCH;  // 160KB persistent stripe cache
    __shared__ float sred[16][4];
    __shared__ float sh_gmax, sh_p, sh_c4;
    __shared__ int   sh_mi, sh_mj;
    __shared__ unsigned int s_lg;

    const int tid = threadIdx.x;
    const int bid = blockIdx.x;

    if (tid == 0) s_lg = d_genv;          // stable: only rewritten at end of prior launch
    __syncthreads();
    unsigned int lg = s_lg;

    // matvec geometry
    const int mb = bid >> 4;              // matrix 0..7 (0..3 = L_k, 4..7 = R_k)
    const int dt = bid & 15;              // d-tile (128 floats)
    const int q  = tid & 31;              // fp32 prepass: float4 column within tile
    const int hs = tid >> 5;              // fp32 prepass: h-segment (16 segs x 128)
    const float4* M4 = nullptr;
    if (bid < NMV)
        M4 = (const float4*)((mb < 4 ? L : R) + (size_t)(mb & 3) * H * H) + (dt * 32 + q);

    // fp16 matvec geometry: 16 col-lanes x 8 cols, 32 h-segs x 64 rows
    const int q16  = tid & 15;
    const int hs32 = tid >> 4;

    // ================= phase 0: prepass (x, h, ones; fp32) + fp16 copy (global + smem rows<640) + init =================
    if (bid < NMV) {
        float* sSx = sb;                  // [0:2048)
        float* sSh = sb + H;              // [2048:4096)
        for (int t = tid; t < H; t += NT) { sSx[t] = x[t]; sSh[t] = h[t]; }
        __syncthreads();
        float4 aX = {0,0,0,0}, aH = {0,0,0,0}, aO = {0,0,0,0};
        const int h0 = hs * 128;
        #pragma unroll 8
        for (int hh = h0; hh < h0 + 128; ++hh) {
            float4 v = M4[(size_t)hh * H4];
            // fp16 scaled copy (x1024)
            union { __half2 h2[2]; uint2 u; } cv;
            cv.h2[0] = __floats2half2_rn(v.x * HSCALE, v.y * HSCALE);
            cv.h2[1] = __floats2half2_rn(v.z * HSCALE, v.w * HSCALE);
            *reinterpret_cast<uint2*>(&d_M16[mb][hh][dt * 128 + q * 4]) = cv.u;
            if (hh < SMROWS)
                *reinterpret_cast<uint2*>(sMat + hh * 256 + q * 8) = cv.u;

            float gx = sSx[hh], gh = sSh[hh];
            aX.x = fmaf(gx, v.x, aX.x); aX.y = fmaf(gx, v.y, aX.y);
            aX.z = fmaf(gx, v.z, aX.z); aX.w = fmaf(gx, v.w, aX.w);
            aH.x = fmaf(gh, v.x, aH.x); aH.y = fmaf(gh, v.y, aH.y);
            aH.z = fmaf(gh, v.z, aH.z); aH.w = fmaf(gh, v.w, aH.w);
            aO.x += v.x; aO.y += v.y; aO.z += v.z; aO.w += v.w;
        }
        int k = mb & 3;
        float4* dstX = (float4*)(mb < 4 ? &d_CLs[0][k][0] : &d_CRs[0][k][0]);
        float4* dstH = (float4*)(mb < 4 ? &d_CLs[1][k][0] : &d_CRs[1][k][0]);
        float4* dstO = (float4*)(mb < 4 ? &d_colL[k][0]   : &d_colR[k][0]);
        // three sequential tree reductions over h-segments
        #pragma unroll
        for (int pass = 0; pass < 3; ++pass) {
            float4 a = (pass == 0) ? aX : (pass == 1) ? aH : aO;
            __syncthreads();
            sacc4[tid] = a;
            __syncthreads();
            #pragma unroll
            for (int off = 8; off > 0; off >>= 1) {
                if (hs < off) {
                    float4 o = sacc4[tid + off * 32];
                    float4 s = sacc4[tid];
                    s.x += o.x; s.y += o.y; s.z += o.z; s.w += o.w;
                    sacc4[tid] = s;
                }
                __syncthreads();
            }
            if (tid < 32) {
                float4* dst = (pass == 0) ? dstX : (pass == 1) ? dstH : dstO;
                dst[dt * 32 + tid] = sacc4[tid];
            }
        }
    } else {
        if (bid == ZERB) {
            for (int t = tid; t < H; t += NT) { d_Sbuf[0][t] = 0.f; d_Sbuf[1][t] = 0.f; }
        }
        if (bid == INIB) {
            float s = 0.f;
            for (int t = tid; t < H; t += NT) s += w[t];
            sb[tid] = s;
            __syncthreads();
            for (int o = NT / 2; o > 0; o >>= 1) {
                if (tid < o) sb[tid] += sb[tid + o];
                __syncthreads();
            }
            if (tid == 0) {
                d_sumw = sb[0];
                d_lc = 0; d_nc = 3; d_npairs = 3;
                d_pi[0] = 0; d_pj[0] = 1;
                d_pi[1] = 0; d_pj[1] = 2;
                d_pi[2] = 1; d_pj[2] = 2;
                d_candSlot[0] = 0; d_candSlot[1] = 1; d_candSlot[2] = ZSLOT;
                d_slotP[0] = 1.f; d_slotC4[0] = 0.f;
                d_slotP[1] = 1.f; d_slotC4[1] = 0.f;
                d_slotP[ZSLOT] = 0.f; d_slotC4[ZSLOT] = 0.f;
            }
        }
    }
    gridbar(lg);

    // ================= 9 iterations =================
    for (int r = 0; r < 9; ++r) {
        // ---------- phase A: combos ----------
        int n = d_npairs * 8;
        float* Sw = &d_Sbuf[r & 1][0];
        float sl0 = 0.f, sl1 = 0.f, sl2 = 0.f, sl3 = 0.f;
        for (int c = bid; c < n; c += NB) {
            int p = c >> 3;
            int k = (c >> 1) & 3;
            int isAdd = c & 1;
            int si = d_candSlot[d_pi[p]];
            int sj = d_candSlot[d_pj[p]];
            float pA = d_slotP[si], cA = d_slotC4[si];
            float pB = d_slotP[sj], cB = d_slotC4[sj];
            const float* bk = b + k * H;

            float amax = 0.f, ssg = 0.f, sth = 0.f, srs = 0.f;
            #pragma unroll
            for (int u = 0; u < 4; ++u) {
                int e = tid + u * NT;
                float cl = pA * fmaf(cA, d_colL[k][e], d_CLs[si][k][e]);
                float cr = pB * fmaf(cB, d_colR[k][e], d_CRs[sj][k][e]);
                float res = isAdd ? ((cl + cr) + bk[e]) : fmaf(cl, cr, bk[e]);
                float uu = fminf(fmaxf(res, -30.f), 30.f);
                float t = __expf(-uu);
                float sg = 1.f / (1.f + t);
                float t2 = t * t;
                float th = (1.f - t2) / (1.f + t2);
                float we = w[e];
                amax = fmaxf(amax, fabsf(res));
                ssg = fmaf(sg, we, ssg);
                sth = fmaf(th, we, sth);
                srs = fmaf(res, we, srs);
                float add = MULTC * (sg + th);
                if (u == 0) sl0 += add; else if (u == 1) sl1 += add;
                else if (u == 2) sl2 += add; else sl3 += add;
            }
            int lane = tid & 31, wid = tid >> 5;
            for (int o = 16; o; o >>= 1) {
                amax = fmaxf(amax, __shfl_down_sync(0xffffffffu, amax, o));
                ssg += __shfl_down_sync(0xffffffffu, ssg, o);
                sth += __shfl_down_sync(0xffffffffu, sth, o);
                srs += __shfl_down_sync(0xffffffffu, srs, o);
            }
            if (lane == 0) { sred[wid][0] = amax; sred[wid][1] = ssg; sred[wid][2] = sth; sred[wid][3] = srs; }
            __syncthreads();
            if (tid == 0) {
                float A = sred[0][0], S1 = sred[0][1], S2 = sred[0][2], S3 = sred[0][3];
                for (int t = 1; t < 16; ++t) {
                    A = fmaxf(A, sred[t][0]); S1 += sred[t][1]; S2 += sred[t][2]; S3 += sred[t][3];
                }
                d_cmax[c] = A; d_ssig[c] = S1; d_stanh[c] = S2; d_sres[c] = S3;
            }
            __syncthreads();
        }
        if (bid < n) {
            atomicAdd(&Sw[tid + 0 * NT], sl0);
            atomicAdd(&Sw[tid + 1 * NT], sl1);
            atomicAdd(&Sw[tid + 2 * NT], sl2);
            atomicAdd(&Sw[tid + 3 * NT], sl3);
        }
        gridbar(lg);

        // ---------- phase B: fp16 matvec(S_r) [0..127]  ||  finalize [128]  ||  zero [129] ----------
        if (bid < NMV && r < 8) {
            // zigzag direction (sweep r+1; prepass was ascending)
            const bool rev = ((r & 1) == 0);
            float* sS = sb;                                // [0:2048) floats
            float4* rlo = dynbuf + 512;                    // [2048:4096) floats
            float4* rhi = dynbuf + 1024;                   // [4096:6144) floats
            for (int t = tid; t < H; t += NT) sS[t] = Sw[t] * INVHSCALE;
            __syncthreads();

            const int hb = hs32 * 64;
            float a0=0,a1=0,a2=0,a3=0,a4=0,a5=0,a6=0,a7=0;
            if (hs32 < SMROWS / 64) {
                // rows served from persistent SMEM (bit-identical values)
                int row = rev ? hb + 63 : hb;
                const int rstep = rev ? -1 : 1;
                #pragma unroll 8
                for (int i = 0; i < 64; ++i) {
                    uint4 u = *reinterpret_cast<const uint4*>(sMat + row * 256 + q16 * 16);
                    float g = sS[row];
                    row += rstep;
                    float2 f0 = __half22float2(*reinterpret_cast<const __half2*>(&u.x));
                    float2 f1 = __half22float2(*reinterpret_cast<const __half2*>(&u.y));
                    float2 f2 = __half22float2(*reinterpret_cast<const __half2*>(&u.z));
                    float2 f3 = __half22float2(*reinterpret_cast<const __half2*>(&u.w));
                    a0 = fmaf(g, f0.x, a0); a1 = fmaf(g, f0.y, a1);
                    a2 = fmaf(g, f1.x, a2); a3 = fmaf(g, f1.y, a3);
                    a4 = fmaf(g, f2.x, a4); a5 = fmaf(g, f2.y, a5);
                    a6 = fmaf(g, f3.x, a6); a7 = fmaf(g, f3.y, a7);
                }
            } else {
                const uint4* Mh = reinterpret_cast<const uint4*>(&d_M16[mb][0][dt * 128]) + q16;
                const uint4* ptr = Mh + (size_t)(rev ? hb + 63 : hb) * (H / 8);
                const ptrdiff_t step = rev ? -(ptrdiff_t)(H / 8) : (ptrdiff_t)(H / 8);
                const float* sSp = rev ? (sS + hb + 63) : (sS + hb);
                const int sstep = rev ? -1 : 1;
                #pragma unroll 8
                for (int i = 0; i < 64; ++i) {
                    uint4 u = *ptr;
                    float g = *sSp;
                    ptr += step; sSp += sstep;
                    float2 f0 = __half22float2(*reinterpret_cast<const __half2*>(&u.x));
                    float2 f1 = __half22float2(*reinterpret_cast<const __half2*>(&u.y));
                    float2 f2 = __half22float2(*reinterpret_cast<const __half2*>(&u.z));
                    float2 f3 = __half22float2(*reinterpret_cast<const __half2*>(&u.w));
                    a0 = fmaf(g, f0.x, a0); a1 = fmaf(g, f0.y, a1);
                    a2 = fmaf(g, f1.x, a2); a3 = fmaf(g, f1.y, a3);
                    a4 = fmaf(g, f2.x, a4); a5 = fmaf(g, f2.y, a5);
                    a6 = fmaf(g, f3.x, a6); a7 = fmaf(g, f3.y, a7);
                }
            }
            float4 alo = make_float4(a0, a1, a2, a3);
            float4 ahi = make_float4(a4, a5, a6, a7);
            __syncthreads();
            rlo[tid] = alo; rhi[tid] = ahi;
            __syncthreads();
            #pragma unroll
            for (int off = 16; off > 0; off >>= 1) {
                if (hs32 < off) {
                    float4 o1 = rlo[tid + off * 16];
                    float4 o2 = rhi[tid + off * 16];
                    alo.x += o1.x; alo.y += o1.y; alo.z += o1.z; alo.w += o1.w;
                    ahi.x += o2.x; ahi.y += o2.y; ahi.z += o2.z; ahi.w += o2.w;
                    rlo[tid] = alo; rhi[tid] = ahi;
                }
                __syncthreads();
            }
            if (hs32 == 0) {
                int k = mb & 3;
                int slot = 2 + r;
                float4* dst = (float4*)(mb < 4 ? &d_CLs[slot][k][0] : &d_CRs[slot][k][0]);
                dst[dt * 32 + q16 * 2]     = rlo[q16];
                dst[dt * 32 + q16 * 2 + 1] = rhi[q16];
            }
        } else if (bid == ZERB) {
            float* Sz = &d_Sbuf[(r + 1) & 1][0];
            for (int t = tid; t < H; t += NT) Sz[t] = 0.f;
        } else if (bid == FINB) {
            // ----- finalize -----
            float* sc4 = sb;                              // [0:2048)
            float* rf  = sb + 2048;                       // [2048:2560)
            float* rmv = sb + 2560;                       // [2560:3072)
            int*   ri  = (int*)(sb + 3072);               // [3072:3584)
            int*   rmk = (int*)(sb + 3584);               // [3584:4096)
            unsigned char* s4 = (unsigned char*)(sb + 4096);  // 512 bytes

            int nn = n;
            float sumw = d_sumw;
            for (int c = tid; c < nn; c += NT) {
                float sr = d_sres[c];
                sc4[c * 4 + 0] = MULTC * d_ssig[c];
                sc4[c * 4 + 1] = MULTC * d_stanh[c];
                sc4[c * 4 + 2] = sumw - sr;
                sc4[c * 4 + 3] = sr;
                s4[c] = (d_cmax[c] < 1.0f) ? 1 : 0;
            }
            __syncthreads();

            // pass 1: argmax (first-occurrence ties) + count4
            float mv = -3.0e38f; int mk = 0x7fffffff; int c4 = 0;
            for (int c = tid; c < nn; c += NT) {
                int cnt = s4[c] ? 4 : 2;
                c4 += (int)s4[c];
                for (int a2 = 0; a2 < cnt; ++a2) {
                    float v = sc4[c * 4 + a2];
                    int key = c * 4 + a2;
                    if (v > mv || (v == mv && key < mk)) { mv = v; mk = key; }
                }
            }
            rmv[tid] = mv; rmk[tid] = mk; ri[tid] = c4;
            __syncthreads();
            for (int s = NT / 2; s > 0; s >>= 1) {
                if (tid < s) {
                    if (rmv[tid + s] > rmv[tid] ||
                        (rmv[tid + s] == rmv[tid] && rmk[tid + s] < rmk[tid])) {
                        rmv[tid] = rmv[tid + s]; rmk[tid] = rmk[tid + s];
                    }
                    ri[tid] += ri[tid + s];
                }
                __syncthreads();
            }
            if (tid == 0) {
                sh_gmax = rmv[0];
                sh_c4 = (float)ri[0];
                int gmc = rmk[0] >> 2;
                sh_mi = d_pi[gmc >> 3];
                sh_mj = d_pj[gmc >> 3];
            }
            __syncthreads();
            float gmax = sh_gmax;
            float s1 = sc4[1];

            // pass 2: sumexp + rank(s1)
            float se = 0.f; int rk = 0;
            for (int c = tid; c < nn; c += NT) {
                int cnt = s4[c] ? 4 : 2;
                for (int a2 = 0; a2 < cnt; ++a2) {
                    float v = sc4[c * 4 + a2];
                    se += expf(v - gmax);
                    rk += (v < s1) ? 1 : 0;
                }
            }
            rf[tid] = se; ri[tid] = rk;
            __syncthreads();
            for (int s = NT / 2; s > 0; s >>= 1) {
                if (tid < s) { rf[tid] += rf[tid + s]; ri[tid] += ri[tid + s]; }
                __syncthreads();
            }
            if (tid == 0) {
                float seT = rf[0];
                int rank = ri[0];
                int tA = d_nc - 2;
                float st = 0.f, ssec = 0.f;
                int cum = 0;
                for (int c = 0; c < nn; ++c) {
                    int cnt = s4[c] ? 4 : 2;
                    if (tA >= cum && tA < cum + cnt)     st   = sc4[c * 4 + (tA - cum)];
                    if (rank >= cum && rank < cum + cnt) ssec = sc4[c * 4 + (rank - cum)];
                    cum += cnt;
                }
                sh_p = expf(st - gmax) / seT;
                out[2048 + 9 * 2048 + 9 + r] = ssec;
            }
            __syncthreads();
            float p = sh_p, c4f = sh_c4;

            float dsw = 0.f;
            for (int e = tid; e < H; e += NT) {
                float Sv = Sw[e];
                float g = p * (Sv + c4f);
                out[2048 + r * 2048 + e] = g;
                if (r == 8) out[e] = g;
                dsw = fmaf(Sv, w[e], dsw);
            }
            rf[tid] = dsw;
            __syncthreads();
            for (int s = NT / 2; s > 0; s >>= 1) {
                if (tid < s) rf[tid] += rf[tid + s];
                __syncthreads();
            }
            if (tid == 0) {
                out[2048 + 9 * 2048 + r] = p * (rf[0] + c4f * d_sumw);

                d_slotP[2 + r] = p;
                d_slotC4[2 + r] = c4f;

                int i = sh_mi, j = sh_mj;
                int lc = d_lc;
                if (i > 2 && j > 2) {
                    d_cs[i - 3] = r;
                    for (int t = j - 3; t < lc - 1; ++t) d_cs[t] = d_cs[t + 1];
                    lc--;
                } else if (i <= 2 && j > 2) {
                    d_cs[j - 3] = r;
                } else {
                    d_cs[lc] = r; lc++;
                }
                d_lc = lc;

                if (r < 8) {
                    int nc2 = 3 + lc;
                    int nri = 9 - (r + 1);
                    int np = 0;
                    for (int a2 = 0; a2 < nc2 - 1; ++a2)
                        for (int bb = a2 + 1; bb < nc2; ++bb) {
                            bool flag;
                            if (nri == lc - 1)      flag = (a2 >= 3);
                            else if (nri == lc)     flag = (bb >= 3);
                            else                    flag = (nri > lc);
                            if (flag) { d_pi[np] = a2; d_pj[np] = bb; ++np; }
                        }
                    d_npairs = np; d_nc = nc2;
                    d_candSlot[0] = 0; d_candSlot[1] = 1; d_candSlot[2] = ZSLOT;
                    for (int t = 0; t < lc; ++t) d_candSlot[3 + t] = 2 + d_cs[t];
                }
            }
        }
        if (r < 8) gridbar(lg);
    }

    // publish quiescent counter value for the next graph replay (idempotent)
    if (tid == 0) d_genv = lg;
}

// ---------------- launch: ONE persistent kernel ----------------
extern "C" void kernel_launch(void* const* d_in, const int* in_sizes, int n_in,
                              void* d_out, int out_size)
{
    const float* x     = (const float*)d_in[0];
    const float* hprev = (const float*)d_in[1];
    const float* L     = (const float*)d_in[2];
    const float* R     = (const float*)d_in[3];
    const float* b     = (const float*)d_in[4];
    const float* w     = (const float*)d_in[5];
    float* out = (float*)d_out;

    static int s_attr_done = 0;
    if (!s_attr_done) {
        cudaFuncSetAttribute(rrnn_kernel,
                             cudaFuncAttributeMaxDynamicSharedMemorySize, SMEM_TOTAL);
        s_attr_done = 1;
    }
    rrnn_kernel<<<NB, NT, SMEM_TOTAL>>>(L, R, x, hprev, b, w, out);
    (void)in_sizes; (void)n_in; (void)out_size;
}